// round 8
// baseline (speedup 1.0000x reference)
#include <cuda_runtime.h>
#include <cuda_bf16.h>
#include <cstdint>

// ---------------- static scratch (allocation-free rule: __device__ globals) ----
__device__ float g_sum[1024];
__device__ float g_sumsq[1024];
__device__ float g_mean[1024];
__device__ float g_rstd[1024];

__device__ float s_h1[8192 * 64];
__device__ __nv_bfloat16 s_h1h[8192 * 64];
__device__ __nv_bfloat16 s_h1l[8192 * 64];
__device__ __nv_bfloat16 s_h2h[8192 * 256];
__device__ __nv_bfloat16 s_h2l[8192 * 256];
__device__ __nv_bfloat16 s_lAh[8192 * 512];
__device__ __nv_bfloat16 s_lAl[8192 * 512];
__device__ __nv_bfloat16 s_wh[1 << 21];
__device__ __nv_bfloat16 s_wl[1 << 21];
__device__ int   s_idx[8192 * 8];
__device__ float s_uv[8192 * 2048];
__device__ __nv_bfloat16 s_aih[67108864];
__device__ __nv_bfloat16 s_ail[67108864];
__device__ float s_bufB[67108864];

// ---------------- helpers -----------------------------------------------------
__device__ __forceinline__ void cp16(uint32_t dst, const void* src) {
    asm volatile("cp.async.ca.shared.global [%0], [%1], 16;\n" :: "r"(dst), "l"(src));
}
__device__ __forceinline__ void bsplit(float x, __nv_bfloat16& h, __nv_bfloat16& l) {
    h = __float2bfloat16(x);
    l = __float2bfloat16(x - __bfloat162float(h));
}
__device__ __forceinline__ uint32_t s2u(const void* p) {
    uint32_t a;
    asm("{ .reg .u64 t; cvta.to.shared.u64 t, %1; cvt.u32.u64 %0, t; }" : "=r"(a) : "l"(p));
    return a;
}
__device__ __forceinline__ void mma16816(float* d, const uint32_t* a, const uint32_t* b) {
    asm volatile(
        "mma.sync.aligned.m16n8k16.row.col.f32.bf16.bf16.f32 "
        "{%0,%1,%2,%3},{%4,%5,%6,%7},{%8,%9},{%0,%1,%2,%3};"
        : "+f"(d[0]), "+f"(d[1]), "+f"(d[2]), "+f"(d[3])
        : "r"(a[0]), "r"(a[1]), "r"(a[2]), "r"(a[3]), "r"(b[0]), "r"(b[1]));
}
__device__ __forceinline__ void ldm_x4(uint32_t& r0, uint32_t& r1, uint32_t& r2,
                                       uint32_t& r3, uint32_t addr) {
    asm volatile("ldmatrix.sync.aligned.m8n8.x4.shared.b16 {%0,%1,%2,%3}, [%4];"
                 : "=r"(r0), "=r"(r1), "=r"(r2), "=r"(r3) : "r"(addr));
}

// ================= bf16x2 split-precision NT GEMM (combined segments) ========
// C = (Ah+Al)*(Bh+Bl)^T dropping Al*Bl.  All 4 operand planes loaded once per
// k-tile; 3 MMA combos accumulate into one register accumulator.
// CTA tile 256x128, 8 warps (64x64 each), k-tile 32, 3-stage cp.async pipeline.
// M%256==0, N%128==0, K%32==0
static constexpr int GLDS    = 40;                     // bf16 row stride (80B)
static constexpr int A_PLANE = 256 * GLDS * 2;         // 20480 B
static constexpr int B_PLANE = 128 * GLDS * 2;         // 10240 B
static constexpr int G_STAGE = 2 * A_PLANE + 2 * B_PLANE;   // 61440 B
static constexpr int G_SMEM  = 3 * G_STAGE;            // 184320 B

__global__ void __launch_bounds__(256, 1) gemm_bf16x2(
        const __nv_bfloat16* __restrict__ Ah, const __nv_bfloat16* __restrict__ Al,
        const __nv_bfloat16* __restrict__ Bh, const __nv_bfloat16* __restrict__ Bl,
        float* __restrict__ C, int M, int N, int K, int do_stats) {
    extern __shared__ __align__(16) char smem[];
    const uint32_t sbase = s2u(smem);
    const int tid = threadIdx.x, lane = tid & 31, wid = tid >> 5;
    const int bm = blockIdx.y * 256, bn = blockIdx.x * 128;
    const int wm = (wid & 3) * 64, wn = (wid >> 2) * 64;

    float acc[4][8][4];
#pragma unroll
    for (int mi = 0; mi < 4; mi++)
#pragma unroll
        for (int ni = 0; ni < 8; ni++)
#pragma unroll
            for (int q = 0; q < 4; q++) acc[mi][ni][q] = 0.f;

    const int aRow = wm + (lane & 15);
    const int aCol = (lane >> 4) << 3;
    const int g = lane >> 3;
    const int bRowOff = ((g >> 1) & 1) * 8 + (lane & 7);
    const int bCol = (g & 1) << 3;

    const int arow_ld = tid >> 2, ach_ld = (tid & 3) << 3;   // A: 256 rows x 4 chunks
    const int nk = K >> 5;

    auto load_tile = [&](int t, int st) {
        const int k0 = t << 5;
        const uint32_t sb = sbase + st * G_STAGE;
        const uint32_t aoff = (uint32_t)arow_ld * 80 + (ach_ld << 1);
        cp16(sb + aoff,            Ah + (size_t)(bm + arow_ld) * K + k0 + ach_ld);
        cp16(sb + A_PLANE + aoff,  Al + (size_t)(bm + arow_ld) * K + k0 + ach_ld);
        const int arow2 = arow_ld + 64;
        const uint32_t aoff2 = (uint32_t)arow2 * 80 + (ach_ld << 1);
        cp16(sb + aoff2,           Ah + (size_t)(bm + arow2) * K + k0 + ach_ld);
        cp16(sb + A_PLANE + aoff2, Al + (size_t)(bm + arow2) * K + k0 + ach_ld);
        const int arow3 = arow_ld + 128;
        const uint32_t aoff3 = (uint32_t)arow3 * 80 + (ach_ld << 1);
        cp16(sb + aoff3,           Ah + (size_t)(bm + arow3) * K + k0 + ach_ld);
        cp16(sb + A_PLANE + aoff3, Al + (size_t)(bm + arow3) * K + k0 + ach_ld);
        const int arow4 = arow_ld + 192;
        const uint32_t aoff4 = (uint32_t)arow4 * 80 + (ach_ld << 1);
        cp16(sb + aoff4,           Ah + (size_t)(bm + arow4) * K + k0 + ach_ld);
        cp16(sb + A_PLANE + aoff4, Al + (size_t)(bm + arow4) * K + k0 + ach_ld);
        // B: 128 rows x 4 chunks = 512 ops over 256 threads = 2 each per plane
        const uint32_t boff = (uint32_t)arow_ld * 80 + (ach_ld << 1);
        cp16(sb + 2 * A_PLANE + boff,           Bh + (size_t)(bn + arow_ld) * K + k0 + ach_ld);
        cp16(sb + 2 * A_PLANE + B_PLANE + boff, Bl + (size_t)(bn + arow_ld) * K + k0 + ach_ld);
        const int brow2 = arow_ld + 64;
        const uint32_t boff2 = (uint32_t)brow2 * 80 + (ach_ld << 1);
        cp16(sb + 2 * A_PLANE + boff2,           Bh + (size_t)(bn + brow2) * K + k0 + ach_ld);
        cp16(sb + 2 * A_PLANE + B_PLANE + boff2, Bl + (size_t)(bn + brow2) * K + k0 + ach_ld);
    };

    load_tile(0, 0);
    asm volatile("cp.async.commit_group;\n" ::: "memory");
    if (nk > 1) load_tile(1, 1);
    asm volatile("cp.async.commit_group;\n" ::: "memory");

    for (int t = 0; t < nk; t++) {
        const int st = t % 3;
        asm volatile("cp.async.wait_group 1;\n" ::: "memory");
        __syncthreads();

        const uint32_t sb = sbase + st * G_STAGE;
        const uint32_t aHi = sb, aLo = sb + A_PLANE;
        const uint32_t bHi = sb + 2 * A_PLANE, bLo = bHi + B_PLANE;
#pragma unroll
        for (int ks = 0; ks < 2; ks++) {
            const int k0 = ks * 16;
            uint32_t ah[4][4], al[4][4], bh[8][2], bl[8][2];
#pragma unroll
            for (int mi = 0; mi < 4; mi++) {
                const uint32_t ro = ((uint32_t)(aRow + mi * 16) * GLDS + k0 + aCol) * 2;
                ldm_x4(ah[mi][0], ah[mi][1], ah[mi][2], ah[mi][3], aHi + ro);
                ldm_x4(al[mi][0], al[mi][1], al[mi][2], al[mi][3], aLo + ro);
            }
#pragma unroll
            for (int p = 0; p < 4; p++) {
                const uint32_t ro = ((uint32_t)(wn + p * 16 + bRowOff) * GLDS + k0 + bCol) * 2;
                ldm_x4(bh[2 * p][0], bh[2 * p][1], bh[2 * p + 1][0], bh[2 * p + 1][1], bHi + ro);
                ldm_x4(bl[2 * p][0], bl[2 * p][1], bl[2 * p + 1][0], bl[2 * p + 1][1], bLo + ro);
            }
#pragma unroll
            for (int mi = 0; mi < 4; mi++)
#pragma unroll
                for (int ni = 0; ni < 8; ni++) {
                    mma16816(acc[mi][ni], al[mi], bh[ni]);
                    mma16816(acc[mi][ni], ah[mi], bl[ni]);
                    mma16816(acc[mi][ni], ah[mi], bh[ni]);
                }
        }
        __syncthreads();
        if (t + 2 < nk) load_tile(t + 2, (t + 2) % 3);
        asm volatile("cp.async.commit_group;\n" ::: "memory");
    }

    // ---- write C
#pragma unroll
    for (int mi = 0; mi < 4; mi++)
#pragma unroll
        for (int ni = 0; ni < 8; ni++) {
            const int r0 = bm + wm + mi * 16 + (lane >> 2);
            const int c0 = bn + wn + ni * 8 + ((lane & 3) << 1);
            *(float2*)&C[(size_t)r0 * N + c0]       = make_float2(acc[mi][ni][0], acc[mi][ni][1]);
            *(float2*)&C[(size_t)(r0 + 8) * N + c0] = make_float2(acc[mi][ni][2], acc[mi][ni][3]);
        }

    // ---- optional fused BN stats
    if (do_stats) {
        float* ssum = (float*)smem;            // reuse stage memory
        float* ssq = ssum + 128;
        __syncthreads();
        if (tid < 128) { ssum[tid] = 0.f; ssq[tid] = 0.f; }
        __syncthreads();
#pragma unroll
        for (int ni = 0; ni < 8; ni++)
#pragma unroll
            for (int par = 0; par < 2; par++) {
                float s = 0.f, sq = 0.f;
#pragma unroll
                for (int mi = 0; mi < 4; mi++) {
                    float v0 = acc[mi][ni][par], v1 = acc[mi][ni][par + 2];
                    s += v0 + v1;
                    sq += v0 * v0 + v1 * v1;
                }
                const int lc0 = wn + ni * 8 + ((lane & 3) << 1) + par;
                atomicAdd(&ssum[lc0], s);
                atomicAdd(&ssq[lc0], sq);
            }
        __syncthreads();
        if (tid < 128) {
            atomicAdd(&g_sum[bn + tid], ssum[tid]);
            atomicAdd(&g_sumsq[bn + tid], ssq[tid]);
        }
    }
}

// ---------------- layer 1: xyz(8192x3) @ W1^T(3x64) -------------------------
__global__ void gemm_k3(const float* __restrict__ xyz, const float* __restrict__ W,
                        float* __restrict__ out) {
    int i = blockIdx.x * 256 + threadIdx.x;
    if (i >= 8192 * 64) return;
    int o = i & 63;
    int m = i >> 6;
    const float* x = xyz + m * 3;
    const float* w = W + o * 3;
    out[i] = x[0] * w[0] + x[1] * w[1] + x[2] * w[2];
}

// ---------------- weight prep ------------------------------------------------
__global__ void prep_w_split(const float* __restrict__ W, __nv_bfloat16* __restrict__ wh,
                             __nv_bfloat16* __restrict__ wl, int total) {
    int i = blockIdx.x * 256 + threadIdx.x;
    if (i >= total) return;
    bsplit(W[i], wh[i], wl[i]);
}

__global__ void prep_wcat_split(const float* __restrict__ W, __nv_bfloat16* __restrict__ wh,
                                __nv_bfloat16* __restrict__ wl, int Cout, int Ch) {
    int i = blockIdx.x * 256 + threadIdx.x;
    if (i >= Cout * Ch) return;
    int o = i / Ch, c = i - o * Ch;
    float a = W[(size_t)o * 2 * Ch + c];
    float r = W[(size_t)o * 2 * Ch + Ch + c];
    bsplit(a, wh[(size_t)o * Ch + c], wl[(size_t)o * Ch + c]);
    bsplit(r - a, wh[(size_t)(Cout + o) * Ch + c], wl[(size_t)(Cout + o) * Ch + c]);
}

// ---------------- batchnorm helpers ------------------------------------------
__global__ void zero_stats() {
    g_sum[threadIdx.x] = 0.f;
    g_sumsq[threadIdx.x] = 0.f;
}

__global__ void bn_stats(const float* __restrict__ x, int rpb, int C) {
    int c = threadIdx.x;
    const float* p = x + (size_t)blockIdx.x * rpb * C + c;
    float s = 0.f, ss = 0.f;
    for (int r = 0; r < rpb; r++) {
        float v = p[(size_t)r * C];
        s += v;
        ss += v * v;
    }
    atomicAdd(&g_sum[c], s);
    atomicAdd(&g_sumsq[c], ss);
}

__global__ void bn_finalize(float inv_n) {
    int c = threadIdx.x;
    float m = g_sum[c] * inv_n;
    float v = g_sumsq[c] * inv_n - m * m;
    g_mean[c] = m;
    g_rstd[c] = rsqrtf(v + 1e-5f);
}

__global__ void bn_apply_split(const float* __restrict__ x, const float* __restrict__ gg,
                               const float* __restrict__ bb, __nv_bfloat16* __restrict__ oh,
                               __nv_bfloat16* __restrict__ ol, int total, int cmask) {
    int i = blockIdx.x * 256 + threadIdx.x;
    if (i >= total) return;
    int c = i & cmask;
    float v = (x[i] - g_mean[c]) * g_rstd[c] * gg[c] + bb[c];
    bsplit(fmaxf(v, 0.f), oh[i], ol[i]);
}

// ---------------- U/V implicit-group stats -----------------------------------
__global__ void uv_stats(const float* __restrict__ UV, const int* __restrict__ idx, int C) {
    const int nc = C >> 8;
    float s[4] = {0.f, 0.f, 0.f, 0.f}, ss[4] = {0.f, 0.f, 0.f, 0.f};
    const int bn0 = blockIdx.x * 32;
    for (int r = 0; r < 32; r++) {
        const int bn = bn0 + r;
        const int b = bn >> 10;
        const int* ip = idx + bn * 8;
        int j[8];
#pragma unroll
        for (int k = 0; k < 8; k++) j[k] = (b << 10) + ip[k];
        const float* Vp = UV + (size_t)bn * 2 * C + C;
#pragma unroll 4
        for (int q = 0; q < nc; q++) {
            const int c = threadIdx.x + (q << 8);
            float v = Vp[c];
#pragma unroll
            for (int k = 0; k < 8; k++) {
                float x = UV[(size_t)j[k] * 2 * C + c] + v;
                s[q] += x;
                ss[q] += x * x;
            }
        }
    }
#pragma unroll 4
    for (int q = 0; q < nc; q++) {
        const int c = threadIdx.x + (q << 8);
        atomicAdd(&g_sum[c], s[q]);
        atomicAdd(&g_sumsq[c], ss[q]);
    }
}

__global__ void uv_combine_split(const float* __restrict__ UV, const int* __restrict__ idx,
                                 const float* __restrict__ gg, const float* __restrict__ bb,
                                 __nv_bfloat16* __restrict__ oh, __nv_bfloat16* __restrict__ ol,
                                 int clog, int total) {
    int i = blockIdx.x * 256 + threadIdx.x;
    if (i >= total) return;
    const int C = 1 << clog;
    int c = i & (C - 1);
    int row = i >> clog;
    int bn = row >> 3;
    int b = bn >> 10;
    int j = (b << 10) + idx[row];
    float u = UV[((size_t)j << (clog + 1)) + c];
    float v = UV[((size_t)bn << (clog + 1)) + C + c];
    float val = (u + v - g_mean[c]) * g_rstd[c] * gg[c] + bb[c];
    bsplit(fmaxf(val, 0.f), oh[i], ol[i]);
}

__global__ void bn_apply_maxpool_split(const float* __restrict__ pre, const float* __restrict__ gg,
                                       const float* __restrict__ bb, __nv_bfloat16* __restrict__ oh,
                                       __nv_bfloat16* __restrict__ ol, int clog, int total) {
    int i = blockIdx.x * 256 + threadIdx.x;
    if (i >= total) return;
    int c = i & ((1 << clog) - 1);
    int bn = i >> clog;
    float m = g_mean[c], r = g_rstd[c] * gg[c], be = bb[c];
    const float* p = pre + (((size_t)bn * 8) << clog) + c;
    float best = 0.f;
#pragma unroll
    for (int k = 0; k < 8; k++) {
        float v = (p[(size_t)k << clog] - m) * r + be;
        best = fmaxf(best, v);
    }
    bsplit(best, oh[i], ol[i]);
}

// final layer: BN+ReLU+maxpool + tiled transpose write out[b, c, n]
__global__ void bn_maxpool_T_tiled(const float* __restrict__ pre, const float* __restrict__ gg,
                                   const float* __restrict__ bb, float* __restrict__ out) {
    __shared__ float tile[32][33];
    const int b = blockIdx.z;
    const int c0 = blockIdx.y * 32;
    const int n0 = blockIdx.x * 32;
    const int tx = threadIdx.x, ty = threadIdx.y;      // (32, 8)
    const int c = c0 + tx;
    const float m = g_mean[c], rr = g_rstd[c] * gg[c], be = bb[c];
#pragma unroll
    for (int s = 0; s < 4; s++) {
        const int nl = ty + s * 8;
        const int bn = (b << 10) + n0 + nl;
        const float* p = pre + (((size_t)bn * 8) << 10) + c;
        float best = 0.f;
#pragma unroll
        for (int k = 0; k < 8; k++) {
            float v = (p[(size_t)k << 10] - m) * rr + be;
            best = fmaxf(best, v);
        }
        tile[nl][tx] = best;
    }
    __syncthreads();
#pragma unroll
    for (int s = 0; s < 4; s++) {
        const int cl = ty + s * 8;
        out[((((size_t)b << 10) | (c0 + cl)) << 10) | (n0 + tx)] = tile[tx][cl];
    }
}

// ---------------- kNN (k=8, includes self) ----------------------------------
__global__ void knn_kernel(const float* __restrict__ xyz, int* __restrict__ idx) {
    __shared__ float sx[1024], sy[1024], sz[1024], ssq[1024];
    int b = blockIdx.y;
    const float* base = xyz + b * 1024 * 3;
    for (int i = threadIdx.x; i < 1024; i += blockDim.x) {
        float x = base[i * 3 + 0], y = base[i * 3 + 1], z = base[i * 3 + 2];
        sx[i] = x; sy[i] = y; sz[i] = z;
        ssq[i] = x * x + y * y + z * z;
    }
    __syncthreads();
    int n = blockIdx.x * blockDim.x + threadIdx.x;
    float px = sx[n], py = sy[n], pz = sz[n], psq = ssq[n];
    float bd[8]; int bi[8];
#pragma unroll
    for (int s = 0; s < 8; s++) { bd[s] = 3.4e38f; bi[s] = 0; }
    int maxslot = 0;
    float worst = 3.4e38f;
    for (int j = 0; j < 1024; j++) {
        float d = (psq + ssq[j]) - 2.f * (px * sx[j] + py * sy[j] + pz * sz[j]);
        if (d < worst) {
#pragma unroll
            for (int s = 0; s < 8; s++) if (s == maxslot) { bd[s] = d; bi[s] = j; }
            worst = bd[0]; maxslot = 0;
#pragma unroll
            for (int s = 1; s < 8; s++) if (bd[s] > worst) { worst = bd[s]; maxslot = s; }
        }
    }
    int o = (b * 1024 + n) * 8;
#pragma unroll
    for (int s = 0; s < 8; s++) idx[o + s] = bi[s];
}

// ---------------- orchestration ---------------------------------------------
extern "C" void kernel_launch(void* const* d_in, const int* in_sizes, int n_in,
                              void* d_out, int out_size) {
    const float* xyz = (const float*)d_in[0];
    const float* W1  = (const float*)d_in[1];
    const float* g1  = (const float*)d_in[2];
    const float* b1  = (const float*)d_in[3];
    const float* W2  = (const float*)d_in[4];
    const float* g2  = (const float*)d_in[5];
    const float* b2  = (const float*)d_in[6];
    const float* WA1 = (const float*)d_in[7];
    const float* gA1 = (const float*)d_in[8];
    const float* bA1 = (const float*)d_in[9];
    const float* WA2 = (const float*)d_in[10];
    const float* gA2 = (const float*)d_in[11];
    const float* bA2 = (const float*)d_in[12];
    const float* WB1 = (const float*)d_in[13];
    const float* gB1 = (const float*)d_in[14];
    const float* bB1 = (const float*)d_in[15];
    const float* WB2 = (const float*)d_in[16];
    const float* gB2 = (const float*)d_in[17];
    const float* bB2 = (const float*)d_in[18];
    float* out = (float*)d_out;

    float *h1, *uv, *bufB;
    __nv_bfloat16 *h1h, *h1l, *h2h, *h2l, *lAh, *lAl, *wh, *wl, *aih, *ail;
    int* idx;
    cudaGetSymbolAddress((void**)&h1,  s_h1);
    cudaGetSymbolAddress((void**)&h1h, s_h1h);
    cudaGetSymbolAddress((void**)&h1l, s_h1l);
    cudaGetSymbolAddress((void**)&h2h, s_h2h);
    cudaGetSymbolAddress((void**)&h2l, s_h2l);
    cudaGetSymbolAddress((void**)&lAh, s_lAh);
    cudaGetSymbolAddress((void**)&lAl, s_lAl);
    cudaGetSymbolAddress((void**)&wh,  s_wh);
    cudaGetSymbolAddress((void**)&wl,  s_wl);
    cudaGetSymbolAddress((void**)&uv,  s_uv);
    cudaGetSymbolAddress((void**)&aih, s_aih);
    cudaGetSymbolAddress((void**)&ail, s_ail);
    cudaGetSymbolAddress((void**)&bufB, s_bufB);
    cudaGetSymbolAddress((void**)&idx, s_idx);

    cudaFuncSetAttribute(gemm_bf16x2, cudaFuncAttributeMaxDynamicSharedMemorySize, G_SMEM);

    // ---- layer 1: 3 -> 64, BN+ReLU -> h1 split
    gemm_k3<<<(8192 * 64) / 256, 256>>>(xyz, W1, h1);
    zero_stats<<<1, 1024>>>();
    bn_stats<<<8192 / 256, 64>>>(h1, 256, 64);
    bn_finalize<<<1, 64>>>(1.f / 8192);
    bn_apply_split<<<(8192 * 64) / 256, 256>>>(h1, g1, b1, h1h, h1l, 8192 * 64, 63);

    // ---- layer 2: 64 -> 256, BN+ReLU -> h2 split (stats fused in GEMM)
    prep_w_split<<<(256 * 64 + 255) / 256, 256>>>(W2, wh, wl, 256 * 64);
    zero_stats<<<1, 1024>>>();
    gemm_bf16x2<<<dim3(2, 32), 256, G_SMEM>>>(h1h, h1l, wh, wl, bufB, 8192, 256, 64, 1);
    bn_finalize<<<1, 256>>>(1.f / 8192);
    bn_apply_split<<<(8192 * 256) / 256, 256>>>(bufB, g2, b2, h2h, h2l, 8192 * 256, 255);

    // ---- kNN on xyz
    knn_kernel<<<dim3(4, 8), 256>>>(xyz, idx);

    // ===== stage A =====
    prep_wcat_split<<<(512 * 256 + 255) / 256, 256>>>(WA1, wh, wl, 512, 256);
    gemm_bf16x2<<<dim3(8, 32), 256, G_SMEM>>>(h2h, h2l, wh, wl, uv, 8192, 1024, 256, 0);
    zero_stats<<<1, 1024>>>();
    uv_stats<<<8192 / 32, 256>>>(uv, idx, 512);
    bn_finalize<<<1, 512>>>(1.f / 65536);
    uv_combine_split<<<(65536 * 512) / 256, 256>>>(uv, idx, gA1, bA1, aih, ail, 9, 65536 * 512);

    prep_w_split<<<(512 * 512 + 255) / 256, 256>>>(WA2, wh, wl, 512 * 512);
    zero_stats<<<1, 1024>>>();
    gemm_bf16x2<<<dim3(4, 256), 256, G_SMEM>>>(aih, ail, wh, wl, bufB, 65536, 512, 512, 1);
    bn_finalize<<<1, 512>>>(1.f / 65536);
    bn_apply_maxpool_split<<<(8192 * 512) / 256, 256>>>(bufB, gA2, bA2, lAh, lAl, 9, 8192 * 512);

    // ===== stage B =====
    prep_wcat_split<<<(1024 * 512 + 255) / 256, 256>>>(WB1, wh, wl, 1024, 512);
    gemm_bf16x2<<<dim3(16, 32), 256, G_SMEM>>>(lAh, lAl, wh, wl, uv, 8192, 2048, 512, 0);
    zero_stats<<<1, 1024>>>();
    uv_stats<<<8192 / 32, 256>>>(uv, idx, 1024);
    bn_finalize<<<1, 1024>>>(1.f / 65536);
    uv_combine_split<<<(65536 * 1024) / 256, 256>>>(uv, idx, gB1, bB1, aih, ail, 10, 65536 * 1024);

    prep_w_split<<<(1024 * 1024 + 255) / 256, 256>>>(WB2, wh, wl, 1024 * 1024);
    zero_stats<<<1, 1024>>>();
    gemm_bf16x2<<<dim3(8, 256), 256, G_SMEM>>>(aih, ail, wh, wl, bufB, 65536, 1024, 1024, 1);
    bn_finalize<<<1, 1024>>>(1.f / 65536);
    bn_maxpool_T_tiled<<<dim3(32, 32, 8), dim3(32, 8)>>>(bufB, gB2, bB2, out);
}

// round 9
// speedup vs baseline: 1.1297x; 1.1297x over previous
#include <cuda_runtime.h>
#include <cuda_bf16.h>
#include <cstdint>

// ---------------- static scratch (allocation-free rule: __device__ globals) ----
__device__ float g_sum[1024];
__device__ float g_sumsq[1024];
__device__ float g_mean[1024];
__device__ float g_rstd[1024];

__device__ float s_h1[8192 * 64];
__device__ __nv_bfloat16 s_h1h[8192 * 64];
__device__ __nv_bfloat16 s_h1l[8192 * 64];
__device__ __nv_bfloat16 s_h2h[8192 * 256];
__device__ __nv_bfloat16 s_h2l[8192 * 256];
__device__ __nv_bfloat16 s_lAh[8192 * 512];
__device__ __nv_bfloat16 s_lAl[8192 * 512];
__device__ __nv_bfloat16 s_wh[1 << 21];
__device__ __nv_bfloat16 s_wl[1 << 21];
__device__ int   s_idx[8192 * 8];
__device__ float s_uv[8192 * 2048];
__device__ __nv_bfloat16 s_aih[67108864];
__device__ __nv_bfloat16 s_ail[67108864];
__device__ float s_bufB[67108864];

// ---------------- helpers -----------------------------------------------------
__device__ __forceinline__ void cp16(uint32_t dst, const void* src) {
    asm volatile("cp.async.ca.shared.global [%0], [%1], 16;\n" :: "r"(dst), "l"(src));
}
__device__ __forceinline__ void bsplit(float x, __nv_bfloat16& h, __nv_bfloat16& l) {
    h = __float2bfloat16(x);
    l = __float2bfloat16(x - __bfloat162float(h));
}
__device__ __forceinline__ uint32_t s2u(const void* p) {
    uint32_t a;
    asm("{ .reg .u64 t; cvta.to.shared.u64 t, %1; cvt.u32.u64 %0, t; }" : "=r"(a) : "l"(p));
    return a;
}
__device__ __forceinline__ void mma16816(float* d, const uint32_t* a, const uint32_t* b) {
    asm volatile(
        "mma.sync.aligned.m16n8k16.row.col.f32.bf16.bf16.f32 "
        "{%0,%1,%2,%3},{%4,%5,%6,%7},{%8,%9},{%0,%1,%2,%3};"
        : "+f"(d[0]), "+f"(d[1]), "+f"(d[2]), "+f"(d[3])
        : "r"(a[0]), "r"(a[1]), "r"(a[2]), "r"(a[3]), "r"(b[0]), "r"(b[1]));
}
__device__ __forceinline__ void ldm_x4(uint32_t& r0, uint32_t& r1, uint32_t& r2,
                                       uint32_t& r3, uint32_t addr) {
    asm volatile("ldmatrix.sync.aligned.m8n8.x4.shared.b16 {%0,%1,%2,%3}, [%4];"
                 : "=r"(r0), "=r"(r1), "=r"(r2), "=r"(r3) : "r"(addr));
}

// ================= bf16x2 split-precision NT GEMM ============================
// C[M,N] = (Ah+Al)[M,K] * (Bh+Bl)[N,K]^T  (3 segments: AlBh, AhBl, AhBh)
// Block 128x128 with 4 warps (warp tile 64x64), k-tile 64, double-buffered
// dynamic smem (2 CTAs/SM).  Optional fused BN-stats epilogue.
// M%128==0, N%128==0, K%64==0
static constexpr int KLDS    = 72;                 // bf16 row stride (144 B)
static constexpr int A_BYTES = 128 * KLDS * 2;     // 18432 B per matrix plane
static constexpr int STAGE2  = 2 * A_BYTES;        // A + B per stage
static constexpr int SMEM2   = 2 * STAGE2;         // 73728 B (double buffer)

__global__ void __launch_bounds__(128, 2) gemm_bf16x2(
        const __nv_bfloat16* __restrict__ Ah, const __nv_bfloat16* __restrict__ Al,
        const __nv_bfloat16* __restrict__ Bh, const __nv_bfloat16* __restrict__ Bl,
        float* __restrict__ C, int M, int N, int K, int do_stats) {
    extern __shared__ __align__(16) char smem[];
    __shared__ float ssum[128], ssq[128];
    const uint32_t sbase = s2u(smem);
    const int tid = threadIdx.x, lane = tid & 31, wid = tid >> 5;
    const int bm = blockIdx.y * 128, bn = blockIdx.x * 128;
    const int wm = (wid & 1) * 64, wn = (wid >> 1) * 64;

    float acc[4][8][4];
#pragma unroll
    for (int mi = 0; mi < 4; mi++)
#pragma unroll
        for (int ni = 0; ni < 8; ni++)
#pragma unroll
            for (int q = 0; q < 4; q++) acc[mi][ni][q] = 0.f;

    const int aRow = wm + (lane & 15);
    const int aCol = (lane >> 4) << 3;
    const int g = lane >> 3;
    const int bRowOff = ((g >> 1) & 1) * 8 + (lane & 7);
    const int bCol = (g & 1) << 3;

    const int lrow = tid >> 3;                 // 0..15
    const int lcol = (tid & 7) << 3;           // bf16 units 0,8,...,56

    const int nk1 = K >> 6;                    // 64-wide k-tiles per segment
    const int nkt = 3 * nk1;

    auto load_tile = [&](int t, int st) {
        const int s = t / nk1;
        const int k0 = (t - s * nk1) << 6;
        const __nv_bfloat16* Asrc = (s == 0) ? Al : Ah;
        const __nv_bfloat16* Bsrc = (s == 1) ? Bl : Bh;
        const uint32_t sb = sbase + (uint32_t)st * STAGE2;
#pragma unroll
        for (int q = 0; q < 8; q++) {
            const int row = lrow + q * 16;
            const uint32_t off = ((uint32_t)row * KLDS + lcol) * 2;
            cp16(sb + off,           Asrc + (size_t)(bm + row) * K + k0 + lcol);
            cp16(sb + A_BYTES + off, Bsrc + (size_t)(bn + row) * K + k0 + lcol);
        }
    };

    load_tile(0, 0);
    asm volatile("cp.async.commit_group;\n" ::: "memory");

    for (int t = 0; t < nkt; t++) {
        const int cur = t & 1, nxt = cur ^ 1;
        if (t + 1 < nkt) load_tile(t + 1, nxt);
        asm volatile("cp.async.commit_group;\n" ::: "memory");
        asm volatile("cp.async.wait_group 1;\n" ::: "memory");
        __syncthreads();

        const uint32_t aPlane = sbase + (uint32_t)cur * STAGE2;
        const uint32_t bPlane = aPlane + A_BYTES;
#pragma unroll
        for (int ks = 0; ks < 4; ks++) {
            const int k0 = ks * 16;
            uint32_t a[4][4], b[8][2];
#pragma unroll
            for (int mi = 0; mi < 4; mi++)
                ldm_x4(a[mi][0], a[mi][1], a[mi][2], a[mi][3],
                       aPlane + ((uint32_t)(aRow + mi * 16) * KLDS + k0 + aCol) * 2);
#pragma unroll
            for (int p = 0; p < 4; p++)
                ldm_x4(b[2 * p][0], b[2 * p][1], b[2 * p + 1][0], b[2 * p + 1][1],
                       bPlane + ((uint32_t)(wn + p * 16 + bRowOff) * KLDS + k0 + bCol) * 2);
#pragma unroll
            for (int mi = 0; mi < 4; mi++)
#pragma unroll
                for (int ni = 0; ni < 8; ni++) mma16816(acc[mi][ni], a[mi], b[ni]);
        }
        __syncthreads();
    }

    // ---- write C
#pragma unroll
    for (int mi = 0; mi < 4; mi++)
#pragma unroll
        for (int ni = 0; ni < 8; ni++) {
            const int r0 = bm + wm + mi * 16 + (lane >> 2);
            const int c0 = bn + wn + ni * 8 + ((lane & 3) << 1);
            *(float2*)&C[(size_t)r0 * N + c0]       = make_float2(acc[mi][ni][0], acc[mi][ni][1]);
            *(float2*)&C[(size_t)(r0 + 8) * N + c0] = make_float2(acc[mi][ni][2], acc[mi][ni][3]);
        }

    // ---- optional fused BN stats
    if (do_stats) {
        ssum[tid] = 0.f;
        ssq[tid] = 0.f;
        __syncthreads();
#pragma unroll
        for (int ni = 0; ni < 8; ni++)
#pragma unroll
            for (int par = 0; par < 2; par++) {
                float s = 0.f, sq = 0.f;
#pragma unroll
                for (int mi = 0; mi < 4; mi++) {
                    float v0 = acc[mi][ni][par], v1 = acc[mi][ni][par + 2];
                    s += v0 + v1;
                    sq += v0 * v0 + v1 * v1;
                }
                const int lc0 = wn + ni * 8 + ((lane & 3) << 1) + par;
                atomicAdd(&ssum[lc0], s);
                atomicAdd(&ssq[lc0], sq);
            }
        __syncthreads();
        atomicAdd(&g_sum[bn + tid], ssum[tid]);
        atomicAdd(&g_sumsq[bn + tid], ssq[tid]);
    }
}

// ---------------- layer 1: xyz(8192x3) @ W1^T(3x64) -------------------------
__global__ void gemm_k3(const float* __restrict__ xyz, const float* __restrict__ W,
                        float* __restrict__ out) {
    int i = blockIdx.x * 256 + threadIdx.x;
    if (i >= 8192 * 64) return;
    int o = i & 63;
    int m = i >> 6;
    const float* x = xyz + m * 3;
    const float* w = W + o * 3;
    out[i] = x[0] * w[0] + x[1] * w[1] + x[2] * w[2];
}

// ---------------- weight prep ------------------------------------------------
__global__ void prep_w_split(const float* __restrict__ W, __nv_bfloat16* __restrict__ wh,
                             __nv_bfloat16* __restrict__ wl, int total) {
    int i = blockIdx.x * 256 + threadIdx.x;
    if (i >= total) return;
    bsplit(W[i], wh[i], wl[i]);
}

__global__ void prep_wcat_split(const float* __restrict__ W, __nv_bfloat16* __restrict__ wh,
                                __nv_bfloat16* __restrict__ wl, int Cout, int Ch) {
    int i = blockIdx.x * 256 + threadIdx.x;
    if (i >= Cout * Ch) return;
    int o = i / Ch, c = i - o * Ch;
    float a = W[(size_t)o * 2 * Ch + c];
    float r = W[(size_t)o * 2 * Ch + Ch + c];
    bsplit(a, wh[(size_t)o * Ch + c], wl[(size_t)o * Ch + c]);
    bsplit(r - a, wh[(size_t)(Cout + o) * Ch + c], wl[(size_t)(Cout + o) * Ch + c]);
}

// ---------------- batchnorm helpers ------------------------------------------
__global__ void bn_stats(const float* __restrict__ x, int rpb, int C) {
    int c = threadIdx.x;
    const float* p = x + (size_t)blockIdx.x * rpb * C + c;
    float s = 0.f, ss = 0.f;
    for (int r = 0; r < rpb; r++) {
        float v = p[(size_t)r * C];
        s += v;
        ss += v * v;
    }
    atomicAdd(&g_sum[c], s);
    atomicAdd(&g_sumsq[c], ss);
}

// finalize + re-zero accumulators (keeps the zero invariant across graph replays)
__global__ void bn_finalize(float inv_n) {
    int c = threadIdx.x;
    float m = g_sum[c] * inv_n;
    float v = g_sumsq[c] * inv_n - m * m;
    g_mean[c] = m;
    g_rstd[c] = rsqrtf(v + 1e-5f);
    g_sum[c] = 0.f;
    g_sumsq[c] = 0.f;
}

__global__ void bn_apply_split(const float* __restrict__ x, const float* __restrict__ gg,
                               const float* __restrict__ bb, __nv_bfloat16* __restrict__ oh,
                               __nv_bfloat16* __restrict__ ol, int total, int cmask) {
    int i = blockIdx.x * 256 + threadIdx.x;
    if (i >= total) return;
    int c = i & cmask;
    float v = (x[i] - g_mean[c]) * g_rstd[c] * gg[c] + bb[c];
    bsplit(fmaxf(v, 0.f), oh[i], ol[i]);
}

// ---------------- U/V implicit-group stats -----------------------------------
__global__ void uv_stats(const float* __restrict__ UV, const int* __restrict__ idx, int C) {
    const int nc = C >> 8;
    float s[4] = {0.f, 0.f, 0.f, 0.f}, ss[4] = {0.f, 0.f, 0.f, 0.f};
    const int bn0 = blockIdx.x * 32;
    for (int r = 0; r < 32; r++) {
        const int bn = bn0 + r;
        const int b = bn >> 10;
        const int* ip = idx + bn * 8;
        int j[8];
#pragma unroll
        for (int k = 0; k < 8; k++) j[k] = (b << 10) + ip[k];
        const float* Vp = UV + (size_t)bn * 2 * C + C;
#pragma unroll 4
        for (int q = 0; q < nc; q++) {
            const int c = threadIdx.x + (q << 8);
            float v = Vp[c];
#pragma unroll
            for (int k = 0; k < 8; k++) {
                float x = UV[(size_t)j[k] * 2 * C + c] + v;
                s[q] += x;
                ss[q] += x * x;
            }
        }
    }
#pragma unroll 4
    for (int q = 0; q < nc; q++) {
        const int c = threadIdx.x + (q << 8);
        atomicAdd(&g_sum[c], s[q]);
        atomicAdd(&g_sumsq[c], ss[q]);
    }
}

__global__ void uv_combine_split(const float* __restrict__ UV, const int* __restrict__ idx,
                                 const float* __restrict__ gg, const float* __restrict__ bb,
                                 __nv_bfloat16* __restrict__ oh, __nv_bfloat16* __restrict__ ol,
                                 int clog, int total) {
    int i = blockIdx.x * 256 + threadIdx.x;
    if (i >= total) return;
    const int C = 1 << clog;
    int c = i & (C - 1);
    int row = i >> clog;
    int bn = row >> 3;
    int b = bn >> 10;
    int j = (b << 10) + idx[row];
    float u = UV[((size_t)j << (clog + 1)) + c];
    float v = UV[((size_t)bn << (clog + 1)) + C + c];
    float val = (u + v - g_mean[c]) * g_rstd[c] * gg[c] + bb[c];
    bsplit(fmaxf(val, 0.f), oh[i], ol[i]);
}

__global__ void bn_apply_maxpool_split(const float* __restrict__ pre, const float* __restrict__ gg,
                                       const float* __restrict__ bb, __nv_bfloat16* __restrict__ oh,
                                       __nv_bfloat16* __restrict__ ol, int clog, int total) {
    int i = blockIdx.x * 256 + threadIdx.x;
    if (i >= total) return;
    int c = i & ((1 << clog) - 1);
    int bn = i >> clog;
    float m = g_mean[c], r = g_rstd[c] * gg[c], be = bb[c];
    const float* p = pre + (((size_t)bn * 8) << clog) + c;
    float best = 0.f;
#pragma unroll
    for (int k = 0; k < 8; k++) {
        float v = (p[(size_t)k << clog] - m) * r + be;
        best = fmaxf(best, v);
    }
    bsplit(best, oh[i], ol[i]);
}

// final layer: BN+ReLU+maxpool + tiled transpose write out[b, c, n]
__global__ void bn_maxpool_T_tiled(const float* __restrict__ pre, const float* __restrict__ gg,
                                   const float* __restrict__ bb, float* __restrict__ out) {
    __shared__ float tile[32][33];
    const int b = blockIdx.z;
    const int c0 = blockIdx.y * 32;
    const int n0 = blockIdx.x * 32;
    const int tx = threadIdx.x, ty = threadIdx.y;      // (32, 8)
    const int c = c0 + tx;
    const float m = g_mean[c], rr = g_rstd[c] * gg[c], be = bb[c];
#pragma unroll
    for (int s = 0; s < 4; s++) {
        const int nl = ty + s * 8;
        const int bn = (b << 10) + n0 + nl;
        const float* p = pre + (((size_t)bn * 8) << 10) + c;
        float best = 0.f;
#pragma unroll
        for (int k = 0; k < 8; k++) {
            float v = (p[(size_t)k << 10] - m) * rr + be;
            best = fmaxf(best, v);
        }
        tile[nl][tx] = best;
    }
    __syncthreads();
#pragma unroll
    for (int s = 0; s < 4; s++) {
        const int cl = ty + s * 8;
        out[((((size_t)b << 10) | (c0 + cl)) << 10) | (n0 + tx)] = tile[tx][cl];
    }
}

// ---------------- kNN (k=8, includes self) ----------------------------------
__global__ void knn_kernel(const float* __restrict__ xyz, int* __restrict__ idx) {
    __shared__ float sx[1024], sy[1024], sz[1024], ssq[1024];
    int b = blockIdx.y;
    const float* base = xyz + b * 1024 * 3;
    for (int i = threadIdx.x; i < 1024; i += blockDim.x) {
        float x = base[i * 3 + 0], y = base[i * 3 + 1], z = base[i * 3 + 2];
        sx[i] = x; sy[i] = y; sz[i] = z;
        ssq[i] = x * x + y * y + z * z;
    }
    __syncthreads();
    int n = blockIdx.x * blockDim.x + threadIdx.x;
    float px = sx[n], py = sy[n], pz = sz[n], psq = ssq[n];
    float bd[8]; int bi[8];
#pragma unroll
    for (int s = 0; s < 8; s++) { bd[s] = 3.4e38f; bi[s] = 0; }
    int maxslot = 0;
    float worst = 3.4e38f;
    for (int j = 0; j < 1024; j++) {
        float d = (psq + ssq[j]) - 2.f * (px * sx[j] + py * sy[j] + pz * sz[j]);
        if (d < worst) {
#pragma unroll
            for (int s = 0; s < 8; s++) if (s == maxslot) { bd[s] = d; bi[s] = j; }
            worst = bd[0]; maxslot = 0;
#pragma unroll
            for (int s = 1; s < 8; s++) if (bd[s] > worst) { worst = bd[s]; maxslot = s; }
        }
    }
    int o = (b * 1024 + n) * 8;
#pragma unroll
    for (int s = 0; s < 8; s++) idx[o + s] = bi[s];
}

// ---------------- orchestration ---------------------------------------------
extern "C" void kernel_launch(void* const* d_in, const int* in_sizes, int n_in,
                              void* d_out, int out_size) {
    const float* xyz = (const float*)d_in[0];
    const float* W1  = (const float*)d_in[1];
    const float* g1  = (const float*)d_in[2];
    const float* b1  = (const float*)d_in[3];
    const float* W2  = (const float*)d_in[4];
    const float* g2  = (const float*)d_in[5];
    const float* b2  = (const float*)d_in[6];
    const float* WA1 = (const float*)d_in[7];
    const float* gA1 = (const float*)d_in[8];
    const float* bA1 = (const float*)d_in[9];
    const float* WA2 = (const float*)d_in[10];
    const float* gA2 = (const float*)d_in[11];
    const float* bA2 = (const float*)d_in[12];
    const float* WB1 = (const float*)d_in[13];
    const float* gB1 = (const float*)d_in[14];
    const float* bB1 = (const float*)d_in[15];
    const float* WB2 = (const float*)d_in[16];
    const float* gB2 = (const float*)d_in[17];
    const float* bB2 = (const float*)d_in[18];
    float* out = (float*)d_out;

    float *h1, *uv, *bufB;
    __nv_bfloat16 *h1h, *h1l, *h2h, *h2l, *lAh, *lAl, *wh, *wl, *aih, *ail;
    int* idx;
    cudaGetSymbolAddress((void**)&h1,  s_h1);
    cudaGetSymbolAddress((void**)&h1h, s_h1h);
    cudaGetSymbolAddress((void**)&h1l, s_h1l);
    cudaGetSymbolAddress((void**)&h2h, s_h2h);
    cudaGetSymbolAddress((void**)&h2l, s_h2l);
    cudaGetSymbolAddress((void**)&lAh, s_lAh);
    cudaGetSymbolAddress((void**)&lAl, s_lAl);
    cudaGetSymbolAddress((void**)&wh,  s_wh);
    cudaGetSymbolAddress((void**)&wl,  s_wl);
    cudaGetSymbolAddress((void**)&uv,  s_uv);
    cudaGetSymbolAddress((void**)&aih, s_aih);
    cudaGetSymbolAddress((void**)&ail, s_ail);
    cudaGetSymbolAddress((void**)&bufB, s_bufB);
    cudaGetSymbolAddress((void**)&idx, s_idx);

    cudaFuncSetAttribute(gemm_bf16x2, cudaFuncAttributeMaxDynamicSharedMemorySize, SMEM2);

    // ---- layer 1: 3 -> 64, BN+ReLU -> h1 split
    gemm_k3<<<(8192 * 64) / 256, 256>>>(xyz, W1, h1);
    bn_stats<<<8192 / 256, 64>>>(h1, 256, 64);
    bn_finalize<<<1, 64>>>(1.f / 8192);
    bn_apply_split<<<(8192 * 64) / 256, 256>>>(h1, g1, b1, h1h, h1l, 8192 * 64, 63);

    // ---- layer 2: 64 -> 256, BN+ReLU -> h2 split (stats fused in GEMM)
    prep_w_split<<<(256 * 64 + 255) / 256, 256>>>(W2, wh, wl, 256 * 64);
    gemm_bf16x2<<<dim3(2, 64), 128, SMEM2>>>(h1h, h1l, wh, wl, bufB, 8192, 256, 64, 1);
    bn_finalize<<<1, 256>>>(1.f / 8192);
    bn_apply_split<<<(8192 * 256) / 256, 256>>>(bufB, g2, b2, h2h, h2l, 8192 * 256, 255);

    // ---- kNN on xyz
    knn_kernel<<<dim3(4, 8), 256>>>(xyz, idx);

    // ===== stage A =====
    prep_wcat_split<<<(512 * 256 + 255) / 256, 256>>>(WA1, wh, wl, 512, 256);
    gemm_bf16x2<<<dim3(8, 64), 128, SMEM2>>>(h2h, h2l, wh, wl, uv, 8192, 1024, 256, 0);
    uv_stats<<<8192 / 32, 256>>>(uv, idx, 512);
    bn_finalize<<<1, 512>>>(1.f / 65536);
    uv_combine_split<<<(65536 * 512) / 256, 256>>>(uv, idx, gA1, bA1, aih, ail, 9, 65536 * 512);

    prep_w_split<<<(512 * 512 + 255) / 256, 256>>>(WA2, wh, wl, 512 * 512);
    gemm_bf16x2<<<dim3(4, 512), 128, SMEM2>>>(aih, ail, wh, wl, bufB, 65536, 512, 512, 1);
    bn_finalize<<<1, 512>>>(1.f / 65536);
    bn_apply_maxpool_split<<<(8192 * 512) / 256, 256>>>(bufB, gA2, bA2, lAh, lAl, 9, 8192 * 512);

    // ===== stage B =====
    prep_wcat_split<<<(1024 * 512 + 255) / 256, 256>>>(WB1, wh, wl, 1024, 512);
    gemm_bf16x2<<<dim3(16, 64), 128, SMEM2>>>(lAh, lAl, wh, wl, uv, 8192, 2048, 512, 0);
    uv_stats<<<8192 / 32, 256>>>(uv, idx, 1024);
    bn_finalize<<<1, 1024>>>(1.f / 65536);
    uv_combine_split<<<(65536 * 1024) / 256, 256>>>(uv, idx, gB1, bB1, aih, ail, 10, 65536 * 1024);

    prep_w_split<<<(1024 * 1024 + 255) / 256, 256>>>(WB2, wh, wl, 1024 * 1024);
    gemm_bf16x2<<<dim3(8, 512), 128, SMEM2>>>(aih, ail, wh, wl, bufB, 65536, 1024, 1024, 1);
    bn_finalize<<<1, 1024>>>(1.f / 65536);
    bn_maxpool_T_tiled<<<dim3(32, 32, 8), dim3(32, 8)>>>(bufB, gB2, bB2, out);
}

// round 10
// speedup vs baseline: 1.3301x; 1.1774x over previous
#include <cuda_runtime.h>
#include <cuda_fp16.h>
#include <cstdint>

// ---------------- static scratch (allocation-free rule: __device__ globals) ----
__device__ float g_sum[1024];
__device__ float g_sumsq[1024];
__device__ float g_mean[1024];
__device__ float g_rstd[1024];

__device__ float s_h1[8192 * 64];
__device__ __half s_h1h[8192 * 64];
__device__ __half s_h1l[8192 * 64];
__device__ __half s_h2h[8192 * 256];
__device__ __half s_h2l[8192 * 256];
__device__ __half s_lAh[8192 * 512];
__device__ __half s_lAl[8192 * 512];
__device__ __half s_wh[1 << 21];
__device__ __half s_wl[1 << 21];
__device__ int   s_idx[8192 * 8];
__device__ float s_uv[8192 * 2048];
__device__ __half s_aih[67108864];
__device__ __half s_ail[67108864];
__device__ float s_bufB[67108864];

// ---------------- helpers -----------------------------------------------------
__device__ __forceinline__ void cp16(uint32_t dst, const void* src) {
    asm volatile("cp.async.ca.shared.global [%0], [%1], 16;\n" :: "r"(dst), "l"(src));
}
__device__ __forceinline__ void hsplit(float x, __half& h, __half& l) {
    h = __float2half_rn(x);
    l = __float2half_rn(x - __half2float(h));
}
__device__ __forceinline__ uint32_t s2u(const void* p) {
    uint32_t a;
    asm("{ .reg .u64 t; cvta.to.shared.u64 t, %1; cvt.u32.u64 %0, t; }" : "=r"(a) : "l"(p));
    return a;
}
__device__ __forceinline__ void mma16816(float* d, const uint32_t* a, const uint32_t* b) {
    asm volatile(
        "mma.sync.aligned.m16n8k16.row.col.f32.f16.f16.f32 "
        "{%0,%1,%2,%3},{%4,%5,%6,%7},{%8,%9},{%0,%1,%2,%3};"
        : "+f"(d[0]), "+f"(d[1]), "+f"(d[2]), "+f"(d[3])
        : "r"(a[0]), "r"(a[1]), "r"(a[2]), "r"(a[3]), "r"(b[0]), "r"(b[1]));
}
__device__ __forceinline__ void ldm_x4(uint32_t& r0, uint32_t& r1, uint32_t& r2,
                                       uint32_t& r3, uint32_t addr) {
    asm volatile("ldmatrix.sync.aligned.m8n8.x4.shared.b16 {%0,%1,%2,%3}, [%4];"
                 : "=r"(r0), "=r"(r1), "=r"(r2), "=r"(r3) : "r"(addr));
}

// ================= fp16x2 split-precision NT GEMM ============================
// C[M,N] = (Ah+Al)[M,K] * (Bh+Bl)[N,K]^T
// nseg==3: segments (Al,Bh), (Ah,Bl), (Ah,Bh)   — ~22-bit accuracy
// nseg==2: segments (Ah,Bl), (Ah,Bh)            — drops Al·Bh (~3e-4 rel)
// Block 128x128, 4 warps (64x64 warp tile), k-tile 64, double-buffered dynamic
// smem (2 CTAs/SM). Optional fused BN-stats epilogue.
// M%128==0, N%128==0, K%64==0
static constexpr int KLDS    = 72;                 // fp16 row stride (144 B)
static constexpr int A_BYTES = 128 * KLDS * 2;     // 18432 B per matrix plane
static constexpr int STAGE2  = 2 * A_BYTES;        // A + B per stage
static constexpr int SMEM2   = 2 * STAGE2;         // 73728 B (double buffer)

__global__ void __launch_bounds__(128, 2) gemm_fp16x2(
        const __half* __restrict__ Ah, const __half* __restrict__ Al,
        const __half* __restrict__ Bh, const __half* __restrict__ Bl,
        float* __restrict__ C, int M, int N, int K, int nseg, int do_stats) {
    extern __shared__ __align__(16) char smem[];
    __shared__ float ssum[128], ssq[128];
    const uint32_t sbase = s2u(smem);
    const int tid = threadIdx.x, lane = tid & 31, wid = tid >> 5;
    const int bm = blockIdx.y * 128, bn = blockIdx.x * 128;
    const int wm = (wid & 1) * 64, wn = (wid >> 1) * 64;

    float acc[4][8][4];
#pragma unroll
    for (int mi = 0; mi < 4; mi++)
#pragma unroll
        for (int ni = 0; ni < 8; ni++)
#pragma unroll
            for (int q = 0; q < 4; q++) acc[mi][ni][q] = 0.f;

    const int aRow = wm + (lane & 15);
    const int aCol = (lane >> 4) << 3;
    const int g = lane >> 3;
    const int bRowOff = ((g >> 1) & 1) * 8 + (lane & 7);
    const int bCol = (g & 1) << 3;

    const int lrow = tid >> 3;                 // 0..15
    const int lcol = (tid & 7) << 3;           // fp16 units 0,8,...,56

    const int nk1 = K >> 6;                    // 64-wide k-tiles per segment
    const int nkt = nseg * nk1;

    auto load_tile = [&](int t, int st) {
        const int s = t / nk1;
        const int k0 = (t - s * nk1) << 6;
        const __half* Asrc = (s == 0 && nseg == 3) ? Al : Ah;
        const __half* Bsrc = (s == nseg - 2) ? Bl : Bh;
        const uint32_t sb = sbase + (uint32_t)st * STAGE2;
#pragma unroll
        for (int q = 0; q < 8; q++) {
            const int row = lrow + q * 16;
            const uint32_t off = ((uint32_t)row * KLDS + lcol) * 2;
            cp16(sb + off,           Asrc + (size_t)(bm + row) * K + k0 + lcol);
            cp16(sb + A_BYTES + off, Bsrc + (size_t)(bn + row) * K + k0 + lcol);
        }
    };

    load_tile(0, 0);
    asm volatile("cp.async.commit_group;\n" ::: "memory");

    for (int t = 0; t < nkt; t++) {
        const int cur = t & 1, nxt = cur ^ 1;
        if (t + 1 < nkt) load_tile(t + 1, nxt);
        asm volatile("cp.async.commit_group;\n" ::: "memory");
        asm volatile("cp.async.wait_group 1;\n" ::: "memory");
        __syncthreads();

        const uint32_t aPlane = sbase + (uint32_t)cur * STAGE2;
        const uint32_t bPlane = aPlane + A_BYTES;
#pragma unroll
        for (int ks = 0; ks < 4; ks++) {
            const int k0 = ks * 16;
            uint32_t a[4][4], b[8][2];
#pragma unroll
            for (int mi = 0; mi < 4; mi++)
                ldm_x4(a[mi][0], a[mi][1], a[mi][2], a[mi][3],
                       aPlane + ((uint32_t)(aRow + mi * 16) * KLDS + k0 + aCol) * 2);
#pragma unroll
            for (int p = 0; p < 4; p++)
                ldm_x4(b[2 * p][0], b[2 * p][1], b[2 * p + 1][0], b[2 * p + 1][1],
                       bPlane + ((uint32_t)(wn + p * 16 + bRowOff) * KLDS + k0 + bCol) * 2);
#pragma unroll
            for (int mi = 0; mi < 4; mi++)
#pragma unroll
                for (int ni = 0; ni < 8; ni++) mma16816(acc[mi][ni], a[mi], b[ni]);
        }
        __syncthreads();
    }

    // ---- write C
#pragma unroll
    for (int mi = 0; mi < 4; mi++)
#pragma unroll
        for (int ni = 0; ni < 8; ni++) {
            const int r0 = bm + wm + mi * 16 + (lane >> 2);
            const int c0 = bn + wn + ni * 8 + ((lane & 3) << 1);
            *(float2*)&C[(size_t)r0 * N + c0]       = make_float2(acc[mi][ni][0], acc[mi][ni][1]);
            *(float2*)&C[(size_t)(r0 + 8) * N + c0] = make_float2(acc[mi][ni][2], acc[mi][ni][3]);
        }

    // ---- optional fused BN stats
    if (do_stats) {
        ssum[tid] = 0.f;
        ssq[tid] = 0.f;
        __syncthreads();
#pragma unroll
        for (int ni = 0; ni < 8; ni++)
#pragma unroll
            for (int par = 0; par < 2; par++) {
                float s = 0.f, sq = 0.f;
#pragma unroll
                for (int mi = 0; mi < 4; mi++) {
                    float v0 = acc[mi][ni][par], v1 = acc[mi][ni][par + 2];
                    s += v0 + v1;
                    sq += v0 * v0 + v1 * v1;
                }
                const int lc0 = wn + ni * 8 + ((lane & 3) << 1) + par;
                atomicAdd(&ssum[lc0], s);
                atomicAdd(&ssq[lc0], sq);
            }
        __syncthreads();
        atomicAdd(&g_sum[bn + tid], ssum[tid]);
        atomicAdd(&g_sumsq[bn + tid], ssq[tid]);
    }
}

// ---------------- layer 1: xyz(8192x3) @ W1^T(3x64) -------------------------
__global__ void gemm_k3(const float* __restrict__ xyz, const float* __restrict__ W,
                        float* __restrict__ out) {
    int i = blockIdx.x * 256 + threadIdx.x;
    if (i >= 8192 * 64) return;
    int o = i & 63;
    int m = i >> 6;
    const float* x = xyz + m * 3;
    const float* w = W + o * 3;
    out[i] = x[0] * w[0] + x[1] * w[1] + x[2] * w[2];
}

// ---------------- weight prep ------------------------------------------------
__global__ void prep_w_split(const float* __restrict__ W, __half* __restrict__ wh,
                             __half* __restrict__ wl, int total) {
    int i = blockIdx.x * 256 + threadIdx.x;
    if (i >= total) return;
    hsplit(W[i], wh[i], wl[i]);
}

__global__ void prep_wcat_split(const float* __restrict__ W, __half* __restrict__ wh,
                                __half* __restrict__ wl, int Cout, int Ch) {
    int i = blockIdx.x * 256 + threadIdx.x;
    if (i >= Cout * Ch) return;
    int o = i / Ch, c = i - o * Ch;
    float a = W[(size_t)o * 2 * Ch + c];
    float r = W[(size_t)o * 2 * Ch + Ch + c];
    hsplit(a, wh[(size_t)o * Ch + c], wl[(size_t)o * Ch + c]);
    hsplit(r - a, wh[(size_t)(Cout + o) * Ch + c], wl[(size_t)(Cout + o) * Ch + c]);
}

// ---------------- batchnorm helpers ------------------------------------------
__global__ void bn_stats(const float* __restrict__ x, int rpb, int C) {
    int c = threadIdx.x;
    const float* p = x + (size_t)blockIdx.x * rpb * C + c;
    float s = 0.f, ss = 0.f;
    for (int r = 0; r < rpb; r++) {
        float v = p[(size_t)r * C];
        s += v;
        ss += v * v;
    }
    atomicAdd(&g_sum[c], s);
    atomicAdd(&g_sumsq[c], ss);
}

// finalize + re-zero accumulators (keeps the zero invariant across graph replays)
__global__ void bn_finalize(float inv_n) {
    int c = threadIdx.x;
    float m = g_sum[c] * inv_n;
    float v = g_sumsq[c] * inv_n - m * m;
    g_mean[c] = m;
    g_rstd[c] = rsqrtf(v + 1e-5f);
    g_sum[c] = 0.f;
    g_sumsq[c] = 0.f;
}

__global__ void bn_apply_split(const float* __restrict__ x, const float* __restrict__ gg,
                               const float* __restrict__ bb, __half* __restrict__ oh,
                               __half* __restrict__ ol, int total, int cmask) {
    int i = blockIdx.x * 256 + threadIdx.x;
    if (i >= total) return;
    int c = i & cmask;
    float v = (x[i] - g_mean[c]) * g_rstd[c] * gg[c] + bb[c];
    hsplit(fmaxf(v, 0.f), oh[i], ol[i]);
}

// ---------------- U/V implicit-group stats -----------------------------------
__global__ void uv_stats(const float* __restrict__ UV, const int* __restrict__ idx, int C) {
    const int nc = C >> 8;
    float s[4] = {0.f, 0.f, 0.f, 0.f}, ss[4] = {0.f, 0.f, 0.f, 0.f};
    const int bn0 = blockIdx.x * 32;
    for (int r = 0; r < 32; r++) {
        const int bn = bn0 + r;
        const int b = bn >> 10;
        const int* ip = idx + bn * 8;
        int j[8];
#pragma unroll
        for (int k = 0; k < 8; k++) j[k] = (b << 10) + ip[k];
        const float* Vp = UV + (size_t)bn * 2 * C + C;
#pragma unroll 4
        for (int q = 0; q < nc; q++) {
            const int c = threadIdx.x + (q << 8);
            float v = Vp[c];
#pragma unroll
            for (int k = 0; k < 8; k++) {
                float x = UV[(size_t)j[k] * 2 * C + c] + v;
                s[q] += x;
                ss[q] += x * x;
            }
        }
    }
#pragma unroll 4
    for (int q = 0; q < nc; q++) {
        const int c = threadIdx.x + (q << 8);
        atomicAdd(&g_sum[c], s[q]);
        atomicAdd(&g_sumsq[c], ss[q]);
    }
}

// combine U[j]+V[n], BN+ReLU, write fp16 hi (+ optional lo)
__global__ void uv_combine_split(const float* __restrict__ UV, const int* __restrict__ idx,
                                 const float* __restrict__ gg, const float* __restrict__ bb,
                                 __half* __restrict__ oh, __half* __restrict__ ol,
                                 int clog, int total, int write_lo) {
    int i = blockIdx.x * 256 + threadIdx.x;
    if (i >= total) return;
    const int C = 1 << clog;
    int c = i & (C - 1);
    int row = i >> clog;
    int bn = row >> 3;
    int b = bn >> 10;
    int j = (b << 10) + idx[row];
    float u = UV[((size_t)j << (clog + 1)) + c];
    float v = UV[((size_t)bn << (clog + 1)) + C + c];
    float val = fmaxf((u + v - g_mean[c]) * g_rstd[c] * gg[c] + bb[c], 0.f);
    __half h = __float2half_rn(val);
    oh[i] = h;
    if (write_lo) ol[i] = __float2half_rn(val - __half2float(h));
}

__global__ void bn_apply_maxpool_split(const float* __restrict__ pre, const float* __restrict__ gg,
                                       const float* __restrict__ bb, __half* __restrict__ oh,
                                       __half* __restrict__ ol, int clog, int total) {
    int i = blockIdx.x * 256 + threadIdx.x;
    if (i >= total) return;
    int c = i & ((1 << clog) - 1);
    int bn = i >> clog;
    float m = g_mean[c], r = g_rstd[c] * gg[c], be = bb[c];
    const float* p = pre + (((size_t)bn * 8) << clog) + c;
    float best = 0.f;
#pragma unroll
    for (int k = 0; k < 8; k++) {
        float v = (p[(size_t)k << clog] - m) * r + be;
        best = fmaxf(best, v);
    }
    hsplit(best, oh[i], ol[i]);
}

// final layer: BN+ReLU+maxpool + tiled transpose write out[b, c, n]
__global__ void bn_maxpool_T_tiled(const float* __restrict__ pre, const float* __restrict__ gg,
                                   const float* __restrict__ bb, float* __restrict__ out) {
    __shared__ float tile[32][33];
    const int b = blockIdx.z;
    const int c0 = blockIdx.y * 32;
    const int n0 = blockIdx.x * 32;
    const int tx = threadIdx.x, ty = threadIdx.y;      // (32, 8)
    const int c = c0 + tx;
    const float m = g_mean[c], rr = g_rstd[c] * gg[c], be = bb[c];
#pragma unroll
    for (int s = 0; s < 4; s++) {
        const int nl = ty + s * 8;
        const int bn = (b << 10) + n0 + nl;
        const float* p = pre + (((size_t)bn * 8) << 10) + c;
        float best = 0.f;
#pragma unroll
        for (int k = 0; k < 8; k++) {
            float v = (p[(size_t)k << 10] - m) * rr + be;
            best = fmaxf(best, v);
        }
        tile[nl][tx] = best;
    }
    __syncthreads();
#pragma unroll
    for (int s = 0; s < 4; s++) {
        const int cl = ty + s * 8;
        out[((((size_t)b << 10) | (c0 + cl)) << 10) | (n0 + tx)] = tile[tx][cl];
    }
}

// ---------------- kNN (k=8, includes self) ----------------------------------
__global__ void knn_kernel(const float* __restrict__ xyz, int* __restrict__ idx) {
    __shared__ float sx[1024], sy[1024], sz[1024], ssq[1024];
    int b = blockIdx.y;
    const float* base = xyz + b * 1024 * 3;
    for (int i = threadIdx.x; i < 1024; i += blockDim.x) {
        float x = base[i * 3 + 0], y = base[i * 3 + 1], z = base[i * 3 + 2];
        sx[i] = x; sy[i] = y; sz[i] = z;
        ssq[i] = x * x + y * y + z * z;
    }
    __syncthreads();
    int n = blockIdx.x * blockDim.x + threadIdx.x;
    float px = sx[n], py = sy[n], pz = sz[n], psq = ssq[n];
    float bd[8]; int bi[8];
#pragma unroll
    for (int s = 0; s < 8; s++) { bd[s] = 3.4e38f; bi[s] = 0; }
    int maxslot = 0;
    float worst = 3.4e38f;
    for (int j = 0; j < 1024; j++) {
        float d = (psq + ssq[j]) - 2.f * (px * sx[j] + py * sy[j] + pz * sz[j]);
        if (d < worst) {
#pragma unroll
            for (int s = 0; s < 8; s++) if (s == maxslot) { bd[s] = d; bi[s] = j; }
            worst = bd[0]; maxslot = 0;
#pragma unroll
            for (int s = 1; s < 8; s++) if (bd[s] > worst) { worst = bd[s]; maxslot = s; }
        }
    }
    int o = (b * 1024 + n) * 8;
#pragma unroll
    for (int s = 0; s < 8; s++) idx[o + s] = bi[s];
}

// ---------------- orchestration ---------------------------------------------
extern "C" void kernel_launch(void* const* d_in, const int* in_sizes, int n_in,
                              void* d_out, int out_size) {
    const float* xyz = (const float*)d_in[0];
    const float* W1  = (const float*)d_in[1];
    const float* g1  = (const float*)d_in[2];
    const float* b1  = (const float*)d_in[3];
    const float* W2  = (const float*)d_in[4];
    const float* g2  = (const float*)d_in[5];
    const float* b2  = (const float*)d_in[6];
    const float* WA1 = (const float*)d_in[7];
    const float* gA1 = (const float*)d_in[8];
    const float* bA1 = (const float*)d_in[9];
    const float* WA2 = (const float*)d_in[10];
    const float* gA2 = (const float*)d_in[11];
    const float* bA2 = (const float*)d_in[12];
    const float* WB1 = (const float*)d_in[13];
    const float* gB1 = (const float*)d_in[14];
    const float* bB1 = (const float*)d_in[15];
    const float* WB2 = (const float*)d_in[16];
    const float* gB2 = (const float*)d_in[17];
    const float* bB2 = (const float*)d_in[18];
    float* out = (float*)d_out;

    float *h1, *uv, *bufB;
    __half *h1h, *h1l, *h2h, *h2l, *lAh, *lAl, *wh, *wl, *aih, *ail;
    int* idx;
    cudaGetSymbolAddress((void**)&h1,  s_h1);
    cudaGetSymbolAddress((void**)&h1h, s_h1h);
    cudaGetSymbolAddress((void**)&h1l, s_h1l);
    cudaGetSymbolAddress((void**)&h2h, s_h2h);
    cudaGetSymbolAddress((void**)&h2l, s_h2l);
    cudaGetSymbolAddress((void**)&lAh, s_lAh);
    cudaGetSymbolAddress((void**)&lAl, s_lAl);
    cudaGetSymbolAddress((void**)&wh,  s_wh);
    cudaGetSymbolAddress((void**)&wl,  s_wl);
    cudaGetSymbolAddress((void**)&uv,  s_uv);
    cudaGetSymbolAddress((void**)&aih, s_aih);
    cudaGetSymbolAddress((void**)&ail, s_ail);
    cudaGetSymbolAddress((void**)&bufB, s_bufB);
    cudaGetSymbolAddress((void**)&idx, s_idx);

    cudaFuncSetAttribute(gemm_fp16x2, cudaFuncAttributeMaxDynamicSharedMemorySize, SMEM2);

    // ---- layer 1: 3 -> 64, BN+ReLU -> h1 split
    gemm_k3<<<(8192 * 64) / 256, 256>>>(xyz, W1, h1);
    bn_stats<<<8192 / 256, 64>>>(h1, 256, 64);
    bn_finalize<<<1, 64>>>(1.f / 8192);
    bn_apply_split<<<(8192 * 64) / 256, 256>>>(h1, g1, b1, h1h, h1l, 8192 * 64, 63);

    // ---- layer 2: 64 -> 256, BN+ReLU -> h2 split (stats fused in GEMM)
    prep_w_split<<<(256 * 64 + 255) / 256, 256>>>(W2, wh, wl, 256 * 64);
    gemm_fp16x2<<<dim3(2, 64), 128, SMEM2>>>(h1h, h1l, wh, wl, bufB, 8192, 256, 64, 3, 1);
    bn_finalize<<<1, 256>>>(1.f / 8192);
    bn_apply_split<<<(8192 * 256) / 256, 256>>>(bufB, g2, b2, h2h, h2l, 8192 * 256, 255);

    // ---- kNN on xyz
    knn_kernel<<<dim3(4, 8), 256>>>(xyz, idx);

    // ===== stage A =====
    prep_wcat_split<<<(512 * 256 + 255) / 256, 256>>>(WA1, wh, wl, 512, 256);
    gemm_fp16x2<<<dim3(8, 64), 128, SMEM2>>>(h2h, h2l, wh, wl, uv, 8192, 1024, 256, 3, 0);
    uv_stats<<<8192 / 32, 256>>>(uv, idx, 512);
    bn_finalize<<<1, 512>>>(1.f / 65536);
    uv_combine_split<<<(65536 * 512) / 256, 256>>>(uv, idx, gA1, bA1, aih, ail, 9,
                                                   65536 * 512, 1);

    prep_w_split<<<(512 * 512 + 255) / 256, 256>>>(WA2, wh, wl, 512 * 512);
    gemm_fp16x2<<<dim3(4, 512), 128, SMEM2>>>(aih, ail, wh, wl, bufB, 65536, 512, 512, 3, 1);
    bn_finalize<<<1, 512>>>(1.f / 65536);
    bn_apply_maxpool_split<<<(8192 * 512) / 256, 256>>>(bufB, gA2, bA2, lAh, lAl, 9, 8192 * 512);

    // ===== stage B =====
    prep_wcat_split<<<(1024 * 512 + 255) / 256, 256>>>(WB1, wh, wl, 1024, 512);
    gemm_fp16x2<<<dim3(16, 64), 128, SMEM2>>>(lAh, lAl, wh, wl, uv, 8192, 2048, 512, 3, 0);
    uv_stats<<<8192 / 32, 256>>>(uv, idx, 1024);
    bn_finalize<<<1, 1024>>>(1.f / 65536);
    uv_combine_split<<<(65536 * 1024) / 256, 256>>>(uv, idx, gB1, bB1, aih, ail, 10,
                                                    65536 * 1024, 0);

    // B2: 2-segment fp16 (drops Al·Bh; Al never read)
    prep_w_split<<<(1024 * 1024 + 255) / 256, 256>>>(WB2, wh, wl, 1024 * 1024);
    gemm_fp16x2<<<dim3(8, 512), 128, SMEM2>>>(aih, ail, wh, wl, bufB, 65536, 1024, 1024, 2, 1);
    bn_finalize<<<1, 1024>>>(1.f / 65536);
    bn_maxpool_T_tiled<<<dim3(32, 32, 8), dim3(32, 8)>>>(bufB, gB2, bB2, out);
}

// round 11
// speedup vs baseline: 1.4916x; 1.1214x over previous
#include <cuda_runtime.h>
#include <cuda_fp16.h>
#include <cstdint>

// ---------------- static scratch (allocation-free rule: __device__ globals) ----
__device__ float g_sum[1024];
__device__ float g_sumsq[1024];
__device__ float g_mean[1024];
__device__ float g_rstd[1024];

__device__ float s_h1[8192 * 64];
__device__ __half s_h1h[8192 * 64];
__device__ __half s_h1l[8192 * 64];
__device__ __half s_h2h[8192 * 256];
__device__ __half s_h2l[8192 * 256];
__device__ __half s_lAh[8192 * 512];
__device__ __half s_wh[1 << 21];
__device__ __half s_wl[1 << 21];
__device__ int   s_idx[8192 * 8];
__device__ float s_uv[8192 * 2048];
__device__ __half s_aih[67108864];
__device__ float s_bufB[67108864];

// ---------------- helpers -----------------------------------------------------
__device__ __forceinline__ void cp16(uint32_t dst, const void* src) {
    asm volatile("cp.async.ca.shared.global [%0], [%1], 16;\n" :: "r"(dst), "l"(src));
}
__device__ __forceinline__ void hsplit(float x, __half& h, __half& l) {
    h = __float2half_rn(x);
    l = __float2half_rn(x - __half2float(h));
}
__device__ __forceinline__ uint32_t s2u(const void* p) {
    uint32_t a;
    asm("{ .reg .u64 t; cvta.to.shared.u64 t, %1; cvt.u32.u64 %0, t; }" : "=r"(a) : "l"(p));
    return a;
}
__device__ __forceinline__ void mma16816(float* d, const uint32_t* a, const uint32_t* b) {
    asm volatile(
        "mma.sync.aligned.m16n8k16.row.col.f32.f16.f16.f32 "
        "{%0,%1,%2,%3},{%4,%5,%6,%7},{%8,%9},{%0,%1,%2,%3};"
        : "+f"(d[0]), "+f"(d[1]), "+f"(d[2]), "+f"(d[3])
        : "r"(a[0]), "r"(a[1]), "r"(a[2]), "r"(a[3]), "r"(b[0]), "r"(b[1]));
}
__device__ __forceinline__ void ldm_x4(uint32_t& r0, uint32_t& r1, uint32_t& r2,
                                       uint32_t& r3, uint32_t addr) {
    asm volatile("ldmatrix.sync.aligned.m8n8.x4.shared.b16 {%0,%1,%2,%3}, [%4];"
                 : "=r"(r0), "=r"(r1), "=r"(r2), "=r"(r3) : "r"(addr));
}

// ================= fp16x2 split-precision NT GEMM ============================
// C[M,N] = (Ah+Al)[M,K] * (Bh+Bl)[N,K]^T
// nseg==3: segments (Al,Bh), (Ah,Bl), (Ah,Bh)
// nseg==2: segments (Ah,Bl), (Ah,Bh)   — drops Al·Bh (Al never read)
// Block 128x128, 4 warps (64x64 warp tile), k-tile 64, double-buffered dynamic
// smem (2 CTAs/SM). Optional fused BN-stats epilogue.
// M%128==0, N%128==0, K%64==0
static constexpr int KLDS    = 72;                 // fp16 row stride (144 B)
static constexpr int A_BYTES = 128 * KLDS * 2;     // 18432 B per matrix plane
static constexpr int STAGE2  = 2 * A_BYTES;        // A + B per stage
static constexpr int SMEM2   = 2 * STAGE2;         // 73728 B (double buffer)

__global__ void __launch_bounds__(128, 2) gemm_fp16x2(
        const __half* __restrict__ Ah, const __half* __restrict__ Al,
        const __half* __restrict__ Bh, const __half* __restrict__ Bl,
        float* __restrict__ C, int M, int N, int K, int nseg, int do_stats) {
    extern __shared__ __align__(16) char smem[];
    __shared__ float ssum[128], ssq[128];
    const uint32_t sbase = s2u(smem);
    const int tid = threadIdx.x, lane = tid & 31, wid = tid >> 5;
    const int bm = blockIdx.y * 128, bn = blockIdx.x * 128;
    const int wm = (wid & 1) * 64, wn = (wid >> 1) * 64;

    float acc[4][8][4];
#pragma unroll
    for (int mi = 0; mi < 4; mi++)
#pragma unroll
        for (int ni = 0; ni < 8; ni++)
#pragma unroll
            for (int q = 0; q < 4; q++) acc[mi][ni][q] = 0.f;

    const int aRow = wm + (lane & 15);
    const int aCol = (lane >> 4) << 3;
    const int g = lane >> 3;
    const int bRowOff = ((g >> 1) & 1) * 8 + (lane & 7);
    const int bCol = (g & 1) << 3;

    const int lrow = tid >> 3;                 // 0..15
    const int lcol = (tid & 7) << 3;           // fp16 units 0,8,...,56

    const int nk1 = K >> 6;                    // 64-wide k-tiles per segment
    const int nkt = nseg * nk1;

    auto load_tile = [&](int t, int st) {
        const int s = t / nk1;
        const int k0 = (t - s * nk1) << 6;
        const __half* Asrc = (s == 0 && nseg == 3) ? Al : Ah;
        const __half* Bsrc = (s == nseg - 2) ? Bl : Bh;
        const uint32_t sb = sbase + (uint32_t)st * STAGE2;
#pragma unroll
        for (int q = 0; q < 8; q++) {
            const int row = lrow + q * 16;
            const uint32_t off = ((uint32_t)row * KLDS + lcol) * 2;
            cp16(sb + off,           Asrc + (size_t)(bm + row) * K + k0 + lcol);
            cp16(sb + A_BYTES + off, Bsrc + (size_t)(bn + row) * K + k0 + lcol);
        }
    };

    load_tile(0, 0);
    asm volatile("cp.async.commit_group;\n" ::: "memory");

    for (int t = 0; t < nkt; t++) {
        const int cur = t & 1, nxt = cur ^ 1;
        if (t + 1 < nkt) load_tile(t + 1, nxt);
        asm volatile("cp.async.commit_group;\n" ::: "memory");
        asm volatile("cp.async.wait_group 1;\n" ::: "memory");
        __syncthreads();

        const uint32_t aPlane = sbase + (uint32_t)cur * STAGE2;
        const uint32_t bPlane = aPlane + A_BYTES;
#pragma unroll
        for (int ks = 0; ks < 4; ks++) {
            const int k0 = ks * 16;
            uint32_t a[4][4], b[8][2];
#pragma unroll
            for (int mi = 0; mi < 4; mi++)
                ldm_x4(a[mi][0], a[mi][1], a[mi][2], a[mi][3],
                       aPlane + ((uint32_t)(aRow + mi * 16) * KLDS + k0 + aCol) * 2);
#pragma unroll
            for (int p = 0; p < 4; p++)
                ldm_x4(b[2 * p][0], b[2 * p][1], b[2 * p + 1][0], b[2 * p + 1][1],
                       bPlane + ((uint32_t)(wn + p * 16 + bRowOff) * KLDS + k0 + bCol) * 2);
#pragma unroll
            for (int mi = 0; mi < 4; mi++)
#pragma unroll
                for (int ni = 0; ni < 8; ni++) mma16816(acc[mi][ni], a[mi], b[ni]);
        }
        __syncthreads();
    }

    // ---- write C
#pragma unroll
    for (int mi = 0; mi < 4; mi++)
#pragma unroll
        for (int ni = 0; ni < 8; ni++) {
            const int r0 = bm + wm + mi * 16 + (lane >> 2);
            const int c0 = bn + wn + ni * 8 + ((lane & 3) << 1);
            *(float2*)&C[(size_t)r0 * N + c0]       = make_float2(acc[mi][ni][0], acc[mi][ni][1]);
            *(float2*)&C[(size_t)(r0 + 8) * N + c0] = make_float2(acc[mi][ni][2], acc[mi][ni][3]);
        }

    // ---- optional fused BN stats
    if (do_stats) {
        ssum[tid] = 0.f;
        ssq[tid] = 0.f;
        __syncthreads();
#pragma unroll
        for (int ni = 0; ni < 8; ni++)
#pragma unroll
            for (int par = 0; par < 2; par++) {
                float s = 0.f, sq = 0.f;
#pragma unroll
                for (int mi = 0; mi < 4; mi++) {
                    float v0 = acc[mi][ni][par], v1 = acc[mi][ni][par + 2];
                    s += v0 + v1;
                    sq += v0 * v0 + v1 * v1;
                }
                const int lc0 = wn + ni * 8 + ((lane & 3) << 1) + par;
                atomicAdd(&ssum[lc0], s);
                atomicAdd(&ssq[lc0], sq);
            }
        __syncthreads();
        atomicAdd(&g_sum[bn + tid], ssum[tid]);
        atomicAdd(&g_sumsq[bn + tid], ssq[tid]);
    }
}

// ---------------- layer 1: xyz(8192x3) @ W1^T(3x64) -------------------------
__global__ void gemm_k3(const float* __restrict__ xyz, const float* __restrict__ W,
                        float* __restrict__ out) {
    int i = blockIdx.x * 256 + threadIdx.x;
    if (i >= 8192 * 64) return;
    int o = i & 63;
    int m = i >> 6;
    const float* x = xyz + m * 3;
    const float* w = W + o * 3;
    out[i] = x[0] * w[0] + x[1] * w[1] + x[2] * w[2];
}

// ---------------- weight prep ------------------------------------------------
__global__ void prep_w_split(const float* __restrict__ W, __half* __restrict__ wh,
                             __half* __restrict__ wl, int total) {
    int i = blockIdx.x * 256 + threadIdx.x;
    if (i >= total) return;
    hsplit(W[i], wh[i], wl[i]);
}

__global__ void prep_wcat_split(const float* __restrict__ W, __half* __restrict__ wh,
                                __half* __restrict__ wl, int Cout, int Ch) {
    int i = blockIdx.x * 256 + threadIdx.x;
    if (i >= Cout * Ch) return;
    int o = i / Ch, c = i - o * Ch;
    float a = W[(size_t)o * 2 * Ch + c];
    float r = W[(size_t)o * 2 * Ch + Ch + c];
    hsplit(a, wh[(size_t)o * Ch + c], wl[(size_t)o * Ch + c]);
    hsplit(r - a, wh[(size_t)(Cout + o) * Ch + c], wl[(size_t)(Cout + o) * Ch + c]);
}

// ---------------- batchnorm helpers ------------------------------------------
__global__ void bn_stats(const float* __restrict__ x, int rpb, int C) {
    int c = threadIdx.x;
    const float* p = x + (size_t)blockIdx.x * rpb * C + c;
    float s = 0.f, ss = 0.f;
    for (int r = 0; r < rpb; r++) {
        float v = p[(size_t)r * C];
        s += v;
        ss += v * v;
    }
    atomicAdd(&g_sum[c], s);
    atomicAdd(&g_sumsq[c], ss);
}

// finalize + re-zero accumulators (keeps the zero invariant across graph replays)
__global__ void bn_finalize(float inv_n) {
    int c = threadIdx.x;
    float m = g_sum[c] * inv_n;
    float v = g_sumsq[c] * inv_n - m * m;
    g_mean[c] = m;
    g_rstd[c] = rsqrtf(v + 1e-5f);
    g_sum[c] = 0.f;
    g_sumsq[c] = 0.f;
}

__global__ void bn_apply_split(const float* __restrict__ x, const float* __restrict__ gg,
                               const float* __restrict__ bb, __half* __restrict__ oh,
                               __half* __restrict__ ol, int total, int cmask) {
    int i = blockIdx.x * 256 + threadIdx.x;
    if (i >= total) return;
    int c = i & cmask;
    float v = (x[i] - g_mean[c]) * g_rstd[c] * gg[c] + bb[c];
    hsplit(fmaxf(v, 0.f), oh[i], ol[i]);
}

// ---------------- U/V implicit-group stats -----------------------------------
__global__ void uv_stats(const float* __restrict__ UV, const int* __restrict__ idx, int C) {
    const int nc = C >> 8;
    float s[4] = {0.f, 0.f, 0.f, 0.f}, ss[4] = {0.f, 0.f, 0.f, 0.f};
    const int bn0 = blockIdx.x * 32;
    for (int r = 0; r < 32; r++) {
        const int bn = bn0 + r;
        const int b = bn >> 10;
        const int* ip = idx + bn * 8;
        int j[8];
#pragma unroll
        for (int k = 0; k < 8; k++) j[k] = (b << 10) + ip[k];
        const float* Vp = UV + (size_t)bn * 2 * C + C;
#pragma unroll 4
        for (int q = 0; q < nc; q++) {
            const int c = threadIdx.x + (q << 8);
            float v = Vp[c];
#pragma unroll
            for (int k = 0; k < 8; k++) {
                float x = UV[(size_t)j[k] * 2 * C + c] + v;
                s[q] += x;
                ss[q] += x * x;
            }
        }
    }
#pragma unroll 4
    for (int q = 0; q < nc; q++) {
        const int c = threadIdx.x + (q << 8);
        atomicAdd(&g_sum[c], s[q]);
        atomicAdd(&g_sumsq[c], ss[q]);
    }
}

// combine U[j]+V[n], BN+ReLU, write fp16 hi only (2 channels/thread)
__global__ void uv_combine_h(const float* __restrict__ UV, const int* __restrict__ idx,
                             const float* __restrict__ gg, const float* __restrict__ bb,
                             __half* __restrict__ oh, int clog, int totalPairs) {
    int p = blockIdx.x * 256 + threadIdx.x;
    if (p >= totalPairs) return;
    const int C = 1 << clog;
    int i = p << 1;
    int c = i & (C - 1);
    int row = i >> clog;
    int bn = row >> 3;
    int b = bn >> 10;
    int j = (b << 10) + idx[row];
    float2 u = *(const float2*)&UV[((size_t)j << (clog + 1)) + c];
    float2 v = *(const float2*)&UV[((size_t)bn << (clog + 1)) + C + c];
    float v0 = fmaxf((u.x + v.x - g_mean[c]) * g_rstd[c] * gg[c] + bb[c], 0.f);
    float v1 = fmaxf((u.y + v.y - g_mean[c + 1]) * g_rstd[c + 1] * gg[c + 1] + bb[c + 1], 0.f);
    *(__half2*)&oh[i] = __floats2half2_rn(v0, v1);
}

// BN+ReLU+max over 8 neighbors, write fp16 hi only
__global__ void bn_apply_maxpool_h(const float* __restrict__ pre, const float* __restrict__ gg,
                                   const float* __restrict__ bb, __half* __restrict__ oh,
                                   int clog, int total) {
    int i = blockIdx.x * 256 + threadIdx.x;
    if (i >= total) return;
    int c = i & ((1 << clog) - 1);
    int bn = i >> clog;
    float m = g_mean[c], r = g_rstd[c] * gg[c], be = bb[c];
    const float* p = pre + (((size_t)bn * 8) << clog) + c;
    float best = 0.f;
#pragma unroll
    for (int k = 0; k < 8; k++) {
        float v = (p[(size_t)k << clog] - m) * r + be;
        best = fmaxf(best, v);
    }
    oh[i] = __float2half_rn(best);
}

// final layer: BN+ReLU+maxpool + tiled transpose write out[b, c, n]
__global__ void bn_maxpool_T_tiled(const float* __restrict__ pre, const float* __restrict__ gg,
                                   const float* __restrict__ bb, float* __restrict__ out) {
    __shared__ float tile[32][33];
    const int b = blockIdx.z;
    const int c0 = blockIdx.y * 32;
    const int n0 = blockIdx.x * 32;
    const int tx = threadIdx.x, ty = threadIdx.y;      // (32, 8)
    const int c = c0 + tx;
    const float m = g_mean[c], rr = g_rstd[c] * gg[c], be = bb[c];
#pragma unroll
    for (int s = 0; s < 4; s++) {
        const int nl = ty + s * 8;
        const int bn = (b << 10) + n0 + nl;
        const float* p = pre + (((size_t)bn * 8) << 10) + c;
        float best = 0.f;
#pragma unroll
        for (int k = 0; k < 8; k++) {
            float v = (p[(size_t)k << 10] - m) * rr + be;
            best = fmaxf(best, v);
        }
        tile[nl][tx] = best;
    }
    __syncthreads();
#pragma unroll
    for (int s = 0; s < 4; s++) {
        const int cl = ty + s * 8;
        out[((((size_t)b << 10) | (c0 + cl)) << 10) | (n0 + tx)] = tile[tx][cl];
    }
}

// ---------------- kNN (k=8, includes self) ----------------------------------
__global__ void knn_kernel(const float* __restrict__ xyz, int* __restrict__ idx) {
    __shared__ float sx[1024], sy[1024], sz[1024], ssq[1024];
    int b = blockIdx.y;
    const float* base = xyz + b * 1024 * 3;
    for (int i = threadIdx.x; i < 1024; i += blockDim.x) {
        float x = base[i * 3 + 0], y = base[i * 3 + 1], z = base[i * 3 + 2];
        sx[i] = x; sy[i] = y; sz[i] = z;
        ssq[i] = x * x + y * y + z * z;
    }
    __syncthreads();
    int n = blockIdx.x * blockDim.x + threadIdx.x;
    float px = sx[n], py = sy[n], pz = sz[n], psq = ssq[n];
    float bd[8]; int bi[8];
#pragma unroll
    for (int s = 0; s < 8; s++) { bd[s] = 3.4e38f; bi[s] = 0; }
    int maxslot = 0;
    float worst = 3.4e38f;
    for (int j = 0; j < 1024; j++) {
        float d = (psq + ssq[j]) - 2.f * (px * sx[j] + py * sy[j] + pz * sz[j]);
        if (d < worst) {
#pragma unroll
            for (int s = 0; s < 8; s++) if (s == maxslot) { bd[s] = d; bi[s] = j; }
            worst = bd[0]; maxslot = 0;
#pragma unroll
            for (int s = 1; s < 8; s++) if (bd[s] > worst) { worst = bd[s]; maxslot = s; }
        }
    }
    int o = (b * 1024 + n) * 8;
#pragma unroll
    for (int s = 0; s < 8; s++) idx[o + s] = bi[s];
}

// ---------------- orchestration ---------------------------------------------
extern "C" void kernel_launch(void* const* d_in, const int* in_sizes, int n_in,
                              void* d_out, int out_size) {
    const float* xyz = (const float*)d_in[0];
    const float* W1  = (const float*)d_in[1];
    const float* g1  = (const float*)d_in[2];
    const float* b1  = (const float*)d_in[3];
    const float* W2  = (const float*)d_in[4];
    const float* g2  = (const float*)d_in[5];
    const float* b2  = (const float*)d_in[6];
    const float* WA1 = (const float*)d_in[7];
    const float* gA1 = (const float*)d_in[8];
    const float* bA1 = (const float*)d_in[9];
    const float* WA2 = (const float*)d_in[10];
    const float* gA2 = (const float*)d_in[11];
    const float* bA2 = (const float*)d_in[12];
    const float* WB1 = (const float*)d_in[13];
    const float* gB1 = (const float*)d_in[14];
    const float* bB1 = (const float*)d_in[15];
    const float* WB2 = (const float*)d_in[16];
    const float* gB2 = (const float*)d_in[17];
    const float* bB2 = (const float*)d_in[18];
    float* out = (float*)d_out;

    float *h1, *uv, *bufB;
    __half *h1h, *h1l, *h2h, *h2l, *lAh, *wh, *wl, *aih;
    int* idx;
    cudaGetSymbolAddress((void**)&h1,  s_h1);
    cudaGetSymbolAddress((void**)&h1h, s_h1h);
    cudaGetSymbolAddress((void**)&h1l, s_h1l);
    cudaGetSymbolAddress((void**)&h2h, s_h2h);
    cudaGetSymbolAddress((void**)&h2l, s_h2l);
    cudaGetSymbolAddress((void**)&lAh, s_lAh);
    cudaGetSymbolAddress((void**)&wh,  s_wh);
    cudaGetSymbolAddress((void**)&wl,  s_wl);
    cudaGetSymbolAddress((void**)&uv,  s_uv);
    cudaGetSymbolAddress((void**)&aih, s_aih);
    cudaGetSymbolAddress((void**)&bufB, s_bufB);
    cudaGetSymbolAddress((void**)&idx, s_idx);

    cudaFuncSetAttribute(gemm_fp16x2, cudaFuncAttributeMaxDynamicSharedMemorySize, SMEM2);

    // ---- layer 1: 3 -> 64, BN+ReLU -> h1 split (L2 GEMM is 3-term: lo kept)
    gemm_k3<<<(8192 * 64) / 256, 256>>>(xyz, W1, h1);
    bn_stats<<<8192 / 256, 64>>>(h1, 256, 64);
    bn_finalize<<<1, 64>>>(1.f / 8192);
    bn_apply_split<<<(8192 * 64) / 256, 256>>>(h1, g1, b1, h1h, h1l, 8192 * 64, 63);

    // ---- layer 2: 64 -> 256 (3-term), BN+ReLU -> h2 split (A1 3-term: lo kept)
    prep_w_split<<<(256 * 64 + 255) / 256, 256>>>(W2, wh, wl, 256 * 64);
    gemm_fp16x2<<<dim3(2, 64), 128, SMEM2>>>(h1h, h1l, wh, wl, bufB, 8192, 256, 64, 3, 1);
    bn_finalize<<<1, 256>>>(1.f / 8192);
    bn_apply_split<<<(8192 * 256) / 256, 256>>>(bufB, g2, b2, h2h, h2l, 8192 * 256, 255);

    // ---- kNN on xyz
    knn_kernel<<<dim3(4, 8), 256>>>(xyz, idx);

    // ===== stage A =====
    // A1 (3-term): UV = h2 @ [WL; WR-WL]^T
    prep_wcat_split<<<(512 * 256 + 255) / 256, 256>>>(WA1, wh, wl, 512, 256);
    gemm_fp16x2<<<dim3(8, 64), 128, SMEM2>>>(h2h, h2l, wh, wl, uv, 8192, 1024, 256, 3, 0);
    uv_stats<<<8192 / 32, 256>>>(uv, idx, 512);
    bn_finalize<<<1, 512>>>(1.f / 65536);
    uv_combine_h<<<(65536 * 256) / 256, 256>>>(uv, idx, gA1, bA1, aih, 9, 65536 * 256);

    // A2 (2-term; activation lo never read)
    prep_w_split<<<(512 * 512 + 255) / 256, 256>>>(WA2, wh, wl, 512 * 512);
    gemm_fp16x2<<<dim3(4, 512), 128, SMEM2>>>(aih, aih, wh, wl, bufB, 65536, 512, 512, 2, 1);
    bn_finalize<<<1, 512>>>(1.f / 65536);
    bn_apply_maxpool_h<<<(8192 * 512) / 256, 256>>>(bufB, gA2, bA2, lAh, 9, 8192 * 512);

    // ===== stage B =====
    // B1 (2-term): UV = lA @ [WL; WR-WL]^T
    prep_wcat_split<<<(1024 * 512 + 255) / 256, 256>>>(WB1, wh, wl, 1024, 512);
    gemm_fp16x2<<<dim3(16, 64), 128, SMEM2>>>(lAh, lAh, wh, wl, uv, 8192, 2048, 512, 2, 0);
    uv_stats<<<8192 / 32, 256>>>(uv, idx, 1024);
    bn_finalize<<<1, 1024>>>(1.f / 65536);
    uv_combine_h<<<(65536 * 512) / 256, 256>>>(uv, idx, gB1, bB1, aih, 10, 65536 * 512);

    // B2 (2-term)
    prep_w_split<<<(1024 * 1024 + 255) / 256, 256>>>(WB2, wh, wl, 1024 * 1024);
    gemm_fp16x2<<<dim3(8, 512), 128, SMEM2>>>(aih, aih, wh, wl, bufB, 65536, 1024, 1024, 2, 1);
    bn_finalize<<<1, 1024>>>(1.f / 65536);
    bn_maxpool_T_tiled<<<dim3(32, 32, 8), dim3(32, 8)>>>(bufB, gB2, bB2, out);
}